// round 14
// baseline (speedup 1.0000x reference)
#include <cuda_runtime.h>
#include <cuda_bf16.h>
#include <cuda_fp16.h>
#include <cstdint>
#include <cstddef>

// ---------------------------------------------------------------------------
// Problem constants
// ---------------------------------------------------------------------------
#define Bq   4
#define Tq   2048
#define Dq   1024
#define Hq   16
#define DHq  64
#define INNERq 1024
#define LOG2E 1.4426950408889634f
#define QSCALE (0.125f * LOG2E)   // fold softmax log2-domain into Q projection

// Blocked-layout sizes (all single fp16 planes)
#define KCq 32                                   // 32-col blocks per 1024-K row panel
#define XBLK 10240                               // activation (128x32) fp16 plane
#define WBLK 10240                               // weight (128x32) fp16 plane
#define WONE_BYTES ((size_t)8 * 32 * WBLK)       // one weight, blocked
#define XPLANE_BYTES ((size_t)64 * 32 * XBLK)    // x / attn-out, blocked
#define QBLK 18432                               // Q (128x64) fp16 plane
#define KVBLK 9216                               // K or V (64x64) fp16 plane
#define QB_BYTES ((size_t)Bq * Hq * 16 * QBLK)
#define KP_BYTES ((size_t)Bq * Hq * 32 * KVBLK)
#define MBLK 16384                               // permuted bf16 mask tile (128x64)
#define MP_BYTES ((size_t)Bq * 16 * 32 * MBLK)

// ---------------------------------------------------------------------------
// Scratch (device globals; allocation is forbidden)
// ---------------------------------------------------------------------------
__device__ __align__(128) unsigned char g_xp[XPLANE_BYTES];
__device__ __align__(128) unsigned char g_ap[XPLANE_BYTES];
__device__ __align__(128) unsigned char g_w[4 * WONE_BYTES];
__device__ __align__(128) unsigned char g_qb[QB_BYTES];
__device__ __align__(128) unsigned char g_kp[KP_BYTES];
__device__ __align__(128) unsigned char g_vp[KP_BYTES];
__device__ __align__(128) unsigned char g_maskp[MP_BYTES];

// ---------------------------------------------------------------------------
// PTX helpers
// ---------------------------------------------------------------------------
__device__ __forceinline__ uint32_t smem_u32(const void* p) {
    uint32_t a;
    asm("{ .reg .u64 t; cvta.to.shared.u64 t, %1; cvt.u32.u64 %0, t; }" : "=r"(a) : "l"(p));
    return a;
}

#define MBAR_INIT(mbar, cnt) \
    asm volatile("mbarrier.init.shared.b64 [%0], %1;" :: "r"((uint32_t)(mbar)), "r"((uint32_t)(cnt)) : "memory")
#define MBAR_EXPECT_TX(mbar, bytes) \
    asm volatile("mbarrier.arrive.expect_tx.shared.b64 _, [%0], %1;" \
                 :: "r"((uint32_t)(mbar)), "r"((uint32_t)(bytes)) : "memory")
#define CP_BULK(smem_dst, gsrc, bytes, mbar) \
    asm volatile("cp.async.bulk.shared::cluster.global.mbarrier::complete_tx::bytes [%0], [%1], %2, [%3];" \
                 :: "r"((uint32_t)(smem_dst)), "l"(gsrc), "r"((uint32_t)(bytes)), \
                    "r"((uint32_t)(mbar)) : "memory")

__device__ __forceinline__ void mbar_wait(uint32_t mbar, uint32_t parity) {
    asm volatile(
        "{\n\t.reg .pred P;\n\t"
        "WAIT_%=:\n\t"
        "mbarrier.try_wait.parity.acquire.cta.shared::cta.b64 P, [%0], %1, 0x989680;\n\t"
        "@P bra DONE_%=;\n\t"
        "bra WAIT_%=;\n\t"
        "DONE_%=:\n\t}"
        :: "r"(mbar), "r"(parity) : "memory");
}

#define LDSM_X4(r0, r1, r2, r3, addr) \
    asm volatile("ldmatrix.sync.aligned.m8n8.x4.shared.b16 {%0,%1,%2,%3}, [%4];" \
                 : "=r"(r0), "=r"(r1), "=r"(r2), "=r"(r3) : "r"(addr))

#define LDSM_X4_T(r0, r1, r2, r3, addr) \
    asm volatile("ldmatrix.sync.aligned.m8n8.x4.trans.shared.b16 {%0,%1,%2,%3}, [%4];" \
                 : "=r"(r0), "=r"(r1), "=r"(r2), "=r"(r3) : "r"(addr))

#define MMA_FP16(c0, c1, c2, c3, a0, a1, a2, a3, b0, b1) \
    asm volatile("mma.sync.aligned.m16n8k16.row.col.f32.f16.f16.f32 " \
                 "{%0,%1,%2,%3}, {%4,%5,%6,%7}, {%8,%9}, {%0,%1,%2,%3};" \
                 : "+f"(c0), "+f"(c1), "+f"(c2), "+f"(c3) \
                 : "r"(a0), "r"(a1), "r"(a2), "r"(a3), "r"(b0), "r"(b1))

__device__ __forceinline__ float ex2f(float x) {
    float r;
    asm("ex2.approx.f32 %0, %1;" : "=f"(r) : "f"(x));
    return r;
}

// ---------------------------------------------------------------------------
// x[8192,1024] fp32 -> blocked single fp16 plane
// ---------------------------------------------------------------------------
__global__ __launch_bounds__(256) void split_kernel(
    const float* __restrict__ in, unsigned char* __restrict__ out)
{
    const int i = (blockIdx.x * 256 + threadIdx.x) * 4;
    float4 v = *reinterpret_cast<const float4*>(in + i);
    const int row = i >> 10, col = i & 1023;
    unsigned char* base = out + ((size_t)((row >> 7) * KCq + (col >> 5))) * XBLK
                        + (row & 127) * 80 + (col & 31) * 2;
    __half2 h01 = __float22half2_rn(make_float2(v.x, v.y));
    __half2 h23 = __float22half2_rn(make_float2(v.z, v.w));
    *reinterpret_cast<uint2*>(base) = make_uint2(
        *reinterpret_cast<uint32_t*>(&h01), *reinterpret_cast<uint32_t*>(&h23));
}

// ---------------------------------------------------------------------------
// All 4 weights in ONE launch: W[K,N] fp32 -> transposed blocked fp16 plane.
// ---------------------------------------------------------------------------
__global__ __launch_bounds__(256) void tsplit_kernel(
    const float* __restrict__ W0, const float* __restrict__ W1,
    const float* __restrict__ W2, const float* __restrict__ W3,
    unsigned char* __restrict__ outbase, int K, int N)
{
    __shared__ float t[32][33];
    const int tx = threadIdx.x, ty = threadIdx.y;
    const int bx = blockIdx.x, by = blockIdx.y, z = blockIdx.z;
    const float* W = (z == 0) ? W0 : (z == 1) ? W1 : (z == 2) ? W2 : W3;
    unsigned char* out = outbase + (size_t)z * WONE_BYTES;
#pragma unroll
    for (int j = 0; j < 32; j += 8)
        t[ty + j][tx] = W[(size_t)(by * 32 + ty + j) * N + bx * 32 + tx];
    __syncthreads();
#pragma unroll
    for (int j = 0; j < 32; j += 8) {
        float v = t[tx][ty + j];
        const int n = bx * 32 + ty + j;
        const int k = by * 32 + tx;
        unsigned char* base = out + ((size_t)((n >> 7) * KCq + (k >> 5))) * WBLK
                            + (n & 127) * 80 + (k & 31) * 2;
        *reinterpret_cast<__half*>(base) = __float2half_rn(v);
    }
}

// ---------------------------------------------------------------------------
// Mask permute: fp32 [B,1,T,T] -> bf16 * log2e, consumer-ordered
// ---------------------------------------------------------------------------
__global__ __launch_bounds__(256) void mask_permute(
    const float* __restrict__ mask, unsigned char* __restrict__ out)
{
    __shared__ float tile[128 * 64];
    const int b = blockIdx.z, qt = blockIdx.y, ch = blockIdx.x;
    const int tid = threadIdx.x;
    const float* src = mask + ((size_t)b * Tq + qt * 128) * Tq + ch * 64;
    for (int i = tid; i < 2048; i += 256) {
        const int row = i >> 4, c4 = (i & 15) * 4;
        float4 v = *reinterpret_cast<const float4*>(src + (size_t)row * Tq + c4);
        tile[row * 64 + c4 + 0] = v.x * LOG2E;
        tile[row * 64 + c4 + 1] = v.y * LOG2E;
        tile[row * 64 + c4 + 2] = v.z * LOG2E;
        tile[row * 64 + c4 + 3] = v.w * LOG2E;
    }
    __syncthreads();
    const int wid = tid >> 5, lane = tid & 31;
    const int r0 = wid * 16 + (lane >> 2);
    const int cb = (lane & 3) * 2;
    uint32_t outv[16];
#pragma unroll
    for (int t = 0; t < 8; ++t)
#pragma unroll
        for (int u = 0; u < 2; ++u) {
            const int row = r0 + u * 8;
            const int c = t * 8 + cb;
            __nv_bfloat162 p = __float22bfloat162_rn(
                make_float2(tile[row * 64 + c], tile[row * 64 + c + 1]));
            outv[t * 2 + u] = *reinterpret_cast<uint32_t*>(&p);
        }
    uint4* dst = reinterpret_cast<uint4*>(
        out + ((size_t)((b * 16 + qt) * 32 + ch)) * MBLK + tid * 64);
#pragma unroll
    for (int i = 0; i < 4; ++i)
        dst[i] = make_uint4(outv[4 * i], outv[4 * i + 1], outv[4 * i + 2], outv[4 * i + 3]);
}

// ---------------------------------------------------------------------------
// bulk-copy GEMM (pure fp16, 4-stage pipeline, GBK=32): C = Ah @ Bh^T.
// ---------------------------------------------------------------------------
#define GBM 128
#define GBN 128
#define GBK 32
#define STAGEB (XBLK + WBLK)              // 20480: A | B
#define GEMM_SMEM (4 * STAGEB + 32)       // 4 stages + 4 mbars

__device__ __forceinline__ void store_qkv(unsigned char* dst, int z, int row, int col,
                                          float v0, float v1) {
    const int b = row >> 11, tok = row & 2047;
    const int h = col >> 6, dh = col & 63;
    size_t off;
    if (z == 0) {
        off = ((size_t)((b * Hq + h) * 16 + (tok >> 7))) * QBLK
            + (size_t)(tok & 127) * 144 + dh * 2;
    } else {
        off = ((size_t)((b * Hq + h) * 32 + (tok >> 6))) * KVBLK
            + (size_t)(tok & 63) * 144 + dh * 2;
    }
    __half2 hh = __float22half2_rn(make_float2(v0, v1));
    *reinterpret_cast<uint32_t*>(dst + off) = *reinterpret_cast<uint32_t*>(&hh);
}

__global__ __launch_bounds__(256, 2) void gemm_bulk_kernel(
    const unsigned char* __restrict__ Aplane, const unsigned char* __restrict__ Wb,
    unsigned char* __restrict__ qb, unsigned char* __restrict__ kp,
    unsigned char* __restrict__ vp,
    float* __restrict__ C, const float* __restrict__ bias,
    int M, int N, int K)
{
    extern __shared__ char smem[];
    const uint32_t sb = smem_u32(smem);
    const uint32_t mbb = sb + 4 * STAGEB;     // 4 mbarriers, 8B apart

    const int tid = threadIdx.x;
    const int wid = tid >> 5;
    const int lane = tid & 31;
    const int warp_m = wid >> 1;
    const int warp_n = wid & 1;
    const int row0 = blockIdx.y * GBM;
    const int col0 = blockIdx.x * GBN;
    const int z = blockIdx.z;
    const int KC = K / GBK;                   // 32

    const unsigned char* Asrc = Aplane + ((size_t)blockIdx.y * KC) * XBLK;
    const unsigned char* Bsrc = (C == nullptr ? Wb + (size_t)z * WONE_BYTES : Wb)
                              + ((size_t)blockIdx.x * KC) * WBLK;

    if (tid == 0) {
#pragma unroll
        for (int s = 0; s < 4; ++s) MBAR_INIT(mbb + 8 * s, 1);
    }
    __syncthreads();

    if (tid == 0) {
#pragma unroll
        for (int s = 0; s < 3; ++s) {
            MBAR_EXPECT_TX(mbb + 8 * s, STAGEB);
            CP_BULK(sb + s * STAGEB, Asrc + (size_t)s * XBLK, XBLK, mbb + 8 * s);
            CP_BULK(sb + s * STAGEB + XBLK, Bsrc + (size_t)s * WBLK, WBLK, mbb + 8 * s);
        }
    }

    float acc[2][8][4];
#pragma unroll
    for (int i = 0; i < 2; ++i)
#pragma unroll
        for (int j = 0; j < 8; ++j)
#pragma unroll
            for (int q = 0; q < 4; ++q) acc[i][j][q] = 0.0f;

    for (int c = 0; c < KC; ++c) {
        if (c + 3 < KC && tid == 0) {
            const int f = c + 3;
            const int s = f & 3;
            MBAR_EXPECT_TX(mbb + 8 * s, STAGEB);
            CP_BULK(sb + s * STAGEB, Asrc + (size_t)f * XBLK, XBLK, mbb + 8 * s);
            CP_BULK(sb + s * STAGEB + XBLK, Bsrc + (size_t)f * WBLK, WBLK, mbb + 8 * s);
        }
        mbar_wait(mbb + 8 * (c & 3), (c >> 2) & 1);

        const uint32_t st = sb + (c & 3) * STAGEB;
        const uint32_t aP = st;
        const uint32_t bP = st + XBLK;

#pragma unroll
        for (int kst = 0; kst < 2; ++kst) {
            const int kb = kst * 32 + (lane >> 4) * 16;

            uint32_t a4[2][4];
#pragma unroll
            for (int mt = 0; mt < 2; ++mt) {
                const int arow = warp_m * 32 + mt * 16 + (lane & 15);
                LDSM_X4(a4[mt][0], a4[mt][1], a4[mt][2], a4[mt][3], aP + arow * 80 + kb);
            }

#pragma unroll
            for (int g = 0; g < 2; ++g) {
                uint32_t b4[4][2];
                const int brow_in = (lane & 7) + ((lane >> 4) << 3);
                const int bkb = kst * 32 + ((lane >> 3) & 1) * 16;
#pragma unroll
                for (int p = 0; p < 2; ++p) {
                    const int nb = warp_n * 64 + g * 32 + p * 16;
                    const uint32_t ba = (nb + brow_in) * 80 + bkb;
                    LDSM_X4(b4[2 * p][0], b4[2 * p][1], b4[2 * p + 1][0], b4[2 * p + 1][1],
                            bP + ba);
                }
#pragma unroll
                for (int mt = 0; mt < 2; ++mt)
#pragma unroll
                    for (int nt = 0; nt < 4; ++nt) {
                        float* cc = acc[mt][g * 4 + nt];
                        MMA_FP16(cc[0], cc[1], cc[2], cc[3],
                                 a4[mt][0], a4[mt][1], a4[mt][2], a4[mt][3],
                                 b4[nt][0], b4[nt][1]);
                    }
            }
        }
        __syncthreads();
    }

    // epilogue
    if (C != nullptr) {
#pragma unroll
        for (int mt = 0; mt < 2; ++mt) {
            const int rbase = row0 + warp_m * 32 + mt * 16 + (lane >> 2);
#pragma unroll
            for (int nt = 0; nt < 8; ++nt) {
                const int cbase = col0 + warp_n * 64 + nt * 8 + (lane & 3) * 2;
                float v0 = acc[mt][nt][0], v1 = acc[mt][nt][1];
                float v2 = acc[mt][nt][2], v3 = acc[mt][nt][3];
                const float b0 = bias[cbase], b1 = bias[cbase + 1];
                v0 += b0; v1 += b1; v2 += b0; v3 += b1;
                *reinterpret_cast<float2*>(C + (size_t)rbase * N + cbase) = make_float2(v0, v1);
                *reinterpret_cast<float2*>(C + (size_t)(rbase + 8) * N + cbase) = make_float2(v2, v3);
            }
        }
    } else {
        const float scale = (z == 0) ? QSCALE : 1.0f;   // Q carries softmax log2-domain
        unsigned char* dst = (z == 0) ? qb : (z == 1) ? kp : vp;
#pragma unroll
        for (int mt = 0; mt < 2; ++mt) {
            const int rbase = row0 + warp_m * 32 + mt * 16 + (lane >> 2);
#pragma unroll
            for (int nt = 0; nt < 8; ++nt) {
                const int cbase = col0 + warp_n * 64 + nt * 8 + (lane & 3) * 2;
                store_qkv(dst, z, rbase, cbase,
                          acc[mt][nt][0] * scale, acc[mt][nt][1] * scale);
                store_qkv(dst, z, rbase + 8, cbase,
                          acc[mt][nt][2] * scale, acc[mt][nt][3] * scale);
            }
        }
    }
}

// ---------------------------------------------------------------------------
// Tensor-core flash attention, pure fp16, 4-stage KV pipeline.
// Softmax in log2 domain: S is (QK+mask)*log2e; P = ex2(S-m) via h2exp2.
// ---------------------------------------------------------------------------
#define FBQ 128
#define FBK 64
#define FROWB 144
#define FQ_TILE (FBQ * FROWB)               // 18432
#define FKV_TILE (FBK * FROWB)              // 9216
#define F_ST FQ_TILE                        // 18432
#define F_STAGE (2 * FKV_TILE)              // 18432 (K | V)
#define FLASH_SMEM (F_ST + 4 * F_STAGE + 64)

__global__ __launch_bounds__(256, 2) void flash_mma_kernel(
    const unsigned char* __restrict__ maskp,
    const unsigned char* __restrict__ qb,
    const unsigned char* __restrict__ kp,
    const unsigned char* __restrict__ vp,
    unsigned char* __restrict__ ap)
{
    extern __shared__ char smem[];
    const uint32_t sb = smem_u32(smem);
    const uint32_t mbQ = sb + F_ST + 4 * F_STAGE;
    const uint32_t mbb = mbQ + 8;            // 4 KV mbarriers

    const int tid  = threadIdx.x;
    const int wid  = tid >> 5;
    const int lane = tid & 31;
    const int qt = blockIdx.x;
    const int h  = blockIdx.y;
    const int b  = blockIdx.z;

    const unsigned char* qsrc = qb + ((size_t)((b * Hq + h) * 16 + qt)) * QBLK;
    const unsigned char* kbase = kp + ((size_t)((b * Hq + h) * 32)) * KVBLK;
    const unsigned char* vbase = vp + ((size_t)((b * Hq + h) * 32)) * KVBLK;
    const unsigned char* mbase = maskp + ((size_t)((b * 16 + qt) * 32)) * MBLK + tid * 64;

    if (tid == 0) {
        MBAR_INIT(mbQ, 1);
#pragma unroll
        for (int s = 0; s < 4; ++s) MBAR_INIT(mbb + 8 * s, 1);
    }
    __syncthreads();

    if (tid == 0) {
        MBAR_EXPECT_TX(mbQ, FQ_TILE);
        CP_BULK(sb, qsrc, FQ_TILE, mbQ);
#pragma unroll
        for (int s = 0; s < 3; ++s) {
            MBAR_EXPECT_TX(mbb + 8 * s, F_STAGE);
            CP_BULK(sb + F_ST + s * F_STAGE, kbase + (size_t)s * KVBLK, KVBLK, mbb + 8 * s);
            CP_BULK(sb + F_ST + s * F_STAGE + FKV_TILE, vbase + (size_t)s * KVBLK, KVBLK,
                    mbb + 8 * s);
        }
    }

    float o[8][4];
#pragma unroll
    for (int t = 0; t < 8; ++t)
#pragma unroll
        for (int j = 0; j < 4; ++j) o[t][j] = 0.0f;
    float m0 = -1e30f, m1 = -1e30f, l0 = 0.0f, l1 = 0.0f;

    const int r0g = qt * FBQ + wid * 16 + (lane >> 2);
    const int quadcol = (lane & 3) * 2;

    mbar_wait(mbQ, 0);

    const int chunks = Tq / FBK;   // 32
    for (int c = 0; c < chunks; ++c) {
        if (c + 3 < chunks && tid == 0) {
            const int f = c + 3;
            const int s = f & 3;
            MBAR_EXPECT_TX(mbb + 8 * s, F_STAGE);
            CP_BULK(sb + F_ST + s * F_STAGE, kbase + (size_t)f * KVBLK, KVBLK, mbb + 8 * s);
            CP_BULK(sb + F_ST + s * F_STAGE + FKV_TILE, vbase + (size_t)f * KVBLK, KVBLK,
                    mbb + 8 * s);
        }
        mbar_wait(mbb + 8 * (c & 3), (c >> 2) & 1);

        const uint32_t st = sb + F_ST + (c & 3) * F_STAGE;
        const uint32_t kP = st;
        const uint32_t vP = st + FKV_TILE;

        // ---- S = Q @ K^T (fp16, 1 pass; S in log2 units) ----
        float s[8][4];
#pragma unroll
        for (int t = 0; t < 8; ++t)
#pragma unroll
            for (int j = 0; j < 4; ++j) s[t][j] = 0.0f;

        const int brow_in = (lane & 7) + ((lane >> 4) << 3);
#pragma unroll
        for (int kk = 0; kk < 4; ++kk) {
            uint32_t q4[4];
            const uint32_t qa = sb + (wid * 16 + (lane & 15)) * FROWB
                              + kk * 32 + (lane >> 4) * 16;
            LDSM_X4(q4[0], q4[1], q4[2], q4[3], qa);

            const int bkb = kk * 32 + ((lane >> 3) & 1) * 16;
#pragma unroll
            for (int p = 0; p < 4; ++p) {
                uint32_t b4[2][2];
                const uint32_t ba = (p * 16 + brow_in) * FROWB + bkb;
                LDSM_X4(b4[0][0], b4[0][1], b4[1][0], b4[1][1], kP + ba);
#pragma unroll
                for (int u = 0; u < 2; ++u) {
                    float* cc = s[2 * p + u];
                    MMA_FP16(cc[0], cc[1], cc[2], cc[3],
                             q4[0], q4[1], q4[2], q4[3], b4[u][0], b4[u][1]);
                }
            }
        }

        // ---- mask (bf16, pre-scaled by log2e) ----
        {
            const uint4* mp = reinterpret_cast<const uint4*>(mbase + (size_t)c * MBLK);
            uint32_t mu[16];
#pragma unroll
            for (int i = 0; i < 4; ++i) {
                uint4 q = mp[i];
                mu[4 * i + 0] = q.x; mu[4 * i + 1] = q.y;
                mu[4 * i + 2] = q.z; mu[4 * i + 3] = q.w;
            }
#pragma unroll
            for (int t = 0; t < 8; ++t) {
                float2 lo2 = __bfloat1622float2(
                    *reinterpret_cast<__nv_bfloat162*>(&mu[2 * t]));
                float2 hi2 = __bfloat1622float2(
                    *reinterpret_cast<__nv_bfloat162*>(&mu[2 * t + 1]));
                s[t][0] += lo2.x; s[t][1] += lo2.y;
                s[t][2] += hi2.x; s[t][3] += hi2.y;
            }
        }

        // ---- online softmax (log2 domain) ----
        float mx0 = -1e30f, mx1 = -1e30f;
#pragma unroll
        for (int t = 0; t < 8; ++t) {
            mx0 = fmaxf(mx0, fmaxf(s[t][0], s[t][1]));
            mx1 = fmaxf(mx1, fmaxf(s[t][2], s[t][3]));
        }
        mx0 = fmaxf(mx0, __shfl_xor_sync(0xffffffffu, mx0, 1));
        mx0 = fmaxf(mx0, __shfl_xor_sync(0xffffffffu, mx0, 2));
        mx1 = fmaxf(mx1, __shfl_xor_sync(0xffffffffu, mx1, 1));
        mx1 = fmaxf(mx1, __shfl_xor_sync(0xffffffffu, mx1, 2));

        const float mn0 = fmaxf(m0, mx0);
        const float mn1 = fmaxf(m1, mx1);
        const float a0 = ex2f(m0 - mn0);
        const float a1 = ex2f(m1 - mn1);
        m0 = mn0; m1 = mn1;

        // ---- P fragments via h2exp2 (fp16x2 MUFU, output IS the fragment) ----
        uint32_t pH[4][4];
        float sum0 = 0.0f, sum1 = 0.0f;
#pragma unroll
        for (int j = 0; j < 4; ++j) {
#pragma unroll
            for (int u = 0; u < 2; ++u) {
                const float mn = u ? mn1 : mn0;
#pragma unroll
                for (int w = 0; w < 2; ++w) {
                    __half2 arg = __floats2half2_rn(
                        s[2 * j + w][2 * u + 0] - mn,
                        s[2 * j + w][2 * u + 1] - mn);
                    __half2 pe = h2exp2(arg);
                    pH[j][2 * w + u] = *reinterpret_cast<uint32_t*>(&pe);
                    float2 pf = __half22float2(pe);
                    if (u == 0) sum0 += pf.x + pf.y;
                    else        sum1 += pf.x + pf.y;
                }
            }
        }
        sum0 += __shfl_xor_sync(0xffffffffu, sum0, 1);
        sum0 += __shfl_xor_sync(0xffffffffu, sum0, 2);
        sum1 += __shfl_xor_sync(0xffffffffu, sum1, 1);
        sum1 += __shfl_xor_sync(0xffffffffu, sum1, 2);
        l0 = l0 * a0 + sum0;
        l1 = l1 * a1 + sum1;

#pragma unroll
        for (int t = 0; t < 8; ++t) {
            o[t][0] *= a0; o[t][1] *= a0;
            o[t][2] *= a1; o[t][3] *= a1;
        }

        // ---- O += P @ V (fp16, 1 pass) ----
#pragma unroll
        for (int j = 0; j < 4; ++j) {
#pragma unroll
            for (int p = 0; p < 4; ++p) {
                uint32_t v4[2][2];
                const uint32_t va = (j * 16 + (lane & 15)) * FROWB
                                  + p * 32 + (lane >> 4) * 16;
                LDSM_X4_T(v4[0][0], v4[0][1], v4[1][0], v4[1][1], vP + va);
#pragma unroll
                for (int u = 0; u < 2; ++u) {
                    float* cc = o[2 * p + u];
                    MMA_FP16(cc[0], cc[1], cc[2], cc[3],
                             pH[j][0], pH[j][1], pH[j][2], pH[j][3],
                             v4[u][0], v4[u][1]);
                }
            }
        }
        __syncthreads();
    }

    // ---- epilogue: normalize, write blocked single fp16 plane A ----
    const float inv0 = 1.0f / l0;
    const float inv1 = 1.0f / l1;
    const int grow = b * Tq + r0g;
#pragma unroll
    for (int t = 0; t < 8; ++t) {
        const int col = h * DHq + t * 8 + quadcol;
        {
            unsigned char* base = ap
                + ((size_t)((grow >> 7) * KCq + (col >> 5))) * XBLK
                + (grow & 127) * 80 + (col & 31) * 2;
            __half2 hh = __float22half2_rn(make_float2(o[t][0] * inv0, o[t][1] * inv0));
            *reinterpret_cast<uint32_t*>(base) = *reinterpret_cast<uint32_t*>(&hh);
        }
        {
            const int grow2 = grow + 8;
            unsigned char* base = ap
                + ((size_t)((grow2 >> 7) * KCq + (col >> 5))) * XBLK
                + (grow2 & 127) * 80 + (col & 31) * 2;
            __half2 hh = __float22half2_rn(make_float2(o[t][2] * inv1, o[t][3] * inv1));
            *reinterpret_cast<uint32_t*>(base) = *reinterpret_cast<uint32_t*>(&hh);
        }
    }
}

// ---------------------------------------------------------------------------
// kernel_launch
// Inputs: x, attention_mask, Wq, Wk, Wv, Wo, bo
// ---------------------------------------------------------------------------
extern "C" void kernel_launch(void* const* d_in, const int* in_sizes, int n_in,
                              void* d_out, int out_size)
{
    (void)in_sizes; (void)n_in; (void)out_size;
    const float* x    = (const float*)d_in[0];
    const float* mask = (const float*)d_in[1];
    const float* Wq   = (const float*)d_in[2];
    const float* Wk   = (const float*)d_in[3];
    const float* Wv   = (const float*)d_in[4];
    const float* Wo   = (const float*)d_in[5];
    const float* bo   = (const float*)d_in[6];
    float* out = (float*)d_out;

    unsigned char *xp, *ap, *w, *qb, *kpb, *vpb, *maskp;
    cudaGetSymbolAddress((void**)&xp, g_xp);
    cudaGetSymbolAddress((void**)&ap, g_ap);
    cudaGetSymbolAddress((void**)&w, g_w);
    cudaGetSymbolAddress((void**)&qb, g_qb);
    cudaGetSymbolAddress((void**)&kpb, g_kp);
    cudaGetSymbolAddress((void**)&vpb, g_vp);
    cudaGetSymbolAddress((void**)&maskp, g_maskp);

    const int M = Bq * Tq;     // 8192
    const int N = INNERq;      // 1024
    const int K = Dq;          // 1024
    const int nx = M * K;

    // Side stream for the mask permute (fork/join is graph-capturable).
    static cudaStream_t s2 = nullptr;
    static cudaEvent_t evFork = nullptr, evJoin = nullptr;
    if (s2 == nullptr) {
        cudaStreamCreateWithFlags(&s2, cudaStreamNonBlocking);
        cudaEventCreateWithFlags(&evFork, cudaEventDisableTiming);
        cudaEventCreateWithFlags(&evJoin, cudaEventDisableTiming);
    }

    cudaEventRecord(evFork, 0);
    cudaStreamWaitEvent(s2, evFork, 0);
    dim3 mGrid(32, 16, Bq);
    mask_permute<<<mGrid, 256, 0, s2>>>(mask, maskp);
    cudaEventRecord(evJoin, s2);

    // main chain: conversions -> blocked layouts
    split_kernel<<<nx / (256 * 4), 256>>>(x, xp);
    dim3 tGrid(N / 32, K / 32, 4), tBlk(32, 8);
    tsplit_kernel<<<tGrid, tBlk>>>(Wq, Wk, Wv, Wo, w, K, N);

    // Q,K,V projections (one launch, 4-stage bulk pipeline, pure fp16)
    cudaFuncSetAttribute(gemm_bulk_kernel,
                         cudaFuncAttributeMaxDynamicSharedMemorySize, GEMM_SMEM);
    dim3 qkvGrid(N / GBN, M / GBM, 3);
    gemm_bulk_kernel<<<qkvGrid, 256, GEMM_SMEM>>>(xp, w, qb, kpb, vpb,
                                                  nullptr, nullptr, M, N, K);

    cudaStreamWaitEvent(0, evJoin, 0);

    // flash attention (pure fp16, 4-stage KV pipeline, log2-domain softmax)
    cudaFuncSetAttribute(flash_mma_kernel,
                         cudaFuncAttributeMaxDynamicSharedMemorySize, FLASH_SMEM);
    dim3 fGrid(Tq / FBQ, Hq, Bq);
    flash_mma_kernel<<<fGrid, 256, FLASH_SMEM>>>(maskp, qb, kpb, vpb, ap);

    // output projection (fp32 + bias, pure fp16)
    dim3 oGrid(N / GBN, M / GBM, 1);
    gemm_bulk_kernel<<<oGrid, 256, GEMM_SMEM>>>(ap, w + 3 * WONE_BYTES,
                                                nullptr, nullptr, nullptr,
                                                out, bo, M, Dq, INNERq);
}

// round 15
// speedup vs baseline: 1.0226x; 1.0226x over previous
#include <cuda_runtime.h>
#include <cuda_bf16.h>
#include <cuda_fp16.h>
#include <cstdint>
#include <cstddef>

// ---------------------------------------------------------------------------
// Problem constants
// ---------------------------------------------------------------------------
#define Bq   4
#define Tq   2048
#define Dq   1024
#define Hq   16
#define DHq  64
#define INNERq 1024
#define SCALEq 0.125f     // 64^-0.5

// Blocked-layout sizes (all single fp16 planes)
#define KCq 32                                   // 32-col blocks per 1024-K row panel
#define XBLK 10240                               // activation (128x32) fp16 plane
#define WBLK 10240                               // weight (128x32) fp16 plane
#define WONE_BYTES ((size_t)8 * 32 * WBLK)       // one weight, blocked
#define XPLANE_BYTES ((size_t)64 * 32 * XBLK)    // x / attn-out, blocked
#define QBLK 18432                               // Q (128x64) fp16 plane
#define KVBLK 9216                               // K or V (64x64) fp16 plane
#define QB_BYTES ((size_t)Bq * Hq * 16 * QBLK)
#define KP_BYTES ((size_t)Bq * Hq * 32 * KVBLK)
#define MBLK 16384                               // permuted bf16 mask tile (128x64)
#define MP_BYTES ((size_t)Bq * 16 * 32 * MBLK)

// ---------------------------------------------------------------------------
// Scratch (device globals; allocation is forbidden)
// ---------------------------------------------------------------------------
__device__ __align__(128) unsigned char g_xp[XPLANE_BYTES];
__device__ __align__(128) unsigned char g_ap[XPLANE_BYTES];
__device__ __align__(128) unsigned char g_w[4 * WONE_BYTES];
__device__ __align__(128) unsigned char g_qb[QB_BYTES];
__device__ __align__(128) unsigned char g_kp[KP_BYTES];
__device__ __align__(128) unsigned char g_vp[KP_BYTES];
__device__ __align__(128) unsigned char g_maskp[MP_BYTES];

// ---------------------------------------------------------------------------
// PTX helpers
// ---------------------------------------------------------------------------
__device__ __forceinline__ uint32_t smem_u32(const void* p) {
    uint32_t a;
    asm("{ .reg .u64 t; cvta.to.shared.u64 t, %1; cvt.u32.u64 %0, t; }" : "=r"(a) : "l"(p));
    return a;
}

#define MBAR_INIT(mbar, cnt) \
    asm volatile("mbarrier.init.shared.b64 [%0], %1;" :: "r"((uint32_t)(mbar)), "r"((uint32_t)(cnt)) : "memory")
#define MBAR_EXPECT_TX(mbar, bytes) \
    asm volatile("mbarrier.arrive.expect_tx.shared.b64 _, [%0], %1;" \
                 :: "r"((uint32_t)(mbar)), "r"((uint32_t)(bytes)) : "memory")
#define CP_BULK(smem_dst, gsrc, bytes, mbar) \
    asm volatile("cp.async.bulk.shared::cluster.global.mbarrier::complete_tx::bytes [%0], [%1], %2, [%3];" \
                 :: "r"((uint32_t)(smem_dst)), "l"(gsrc), "r"((uint32_t)(bytes)), \
                    "r"((uint32_t)(mbar)) : "memory")

__device__ __forceinline__ void mbar_wait(uint32_t mbar, uint32_t parity) {
    asm volatile(
        "{\n\t.reg .pred P;\n\t"
        "WAIT_%=:\n\t"
        "mbarrier.try_wait.parity.acquire.cta.shared::cta.b64 P, [%0], %1, 0x989680;\n\t"
        "@P bra DONE_%=;\n\t"
        "bra WAIT_%=;\n\t"
        "DONE_%=:\n\t}"
        :: "r"(mbar), "r"(parity) : "memory");
}

#define LDSM_X4(r0, r1, r2, r3, addr) \
    asm volatile("ldmatrix.sync.aligned.m8n8.x4.shared.b16 {%0,%1,%2,%3}, [%4];" \
                 : "=r"(r0), "=r"(r1), "=r"(r2), "=r"(r3) : "r"(addr))

#define LDSM_X4_T(r0, r1, r2, r3, addr) \
    asm volatile("ldmatrix.sync.aligned.m8n8.x4.trans.shared.b16 {%0,%1,%2,%3}, [%4];" \
                 : "=r"(r0), "=r"(r1), "=r"(r2), "=r"(r3) : "r"(addr))

#define MMA_FP16(c0, c1, c2, c3, a0, a1, a2, a3, b0, b1) \
    asm volatile("mma.sync.aligned.m16n8k16.row.col.f32.f16.f16.f32 " \
                 "{%0,%1,%2,%3}, {%4,%5,%6,%7}, {%8,%9}, {%0,%1,%2,%3};" \
                 : "+f"(c0), "+f"(c1), "+f"(c2), "+f"(c3) \
                 : "r"(a0), "r"(a1), "r"(a2), "r"(a3), "r"(b0), "r"(b1))

// ---------------------------------------------------------------------------
// x[8192,1024] fp32 -> blocked single fp16 plane
// ---------------------------------------------------------------------------
__global__ __launch_bounds__(256) void split_kernel(
    const float* __restrict__ in, unsigned char* __restrict__ out)
{
    const int i = (blockIdx.x * 256 + threadIdx.x) * 4;
    float4 v = *reinterpret_cast<const float4*>(in + i);
    const int row = i >> 10, col = i & 1023;
    unsigned char* base = out + ((size_t)((row >> 7) * KCq + (col >> 5))) * XBLK
                        + (row & 127) * 80 + (col & 31) * 2;
    __half2 h01 = __float22half2_rn(make_float2(v.x, v.y));
    __half2 h23 = __float22half2_rn(make_float2(v.z, v.w));
    *reinterpret_cast<uint2*>(base) = make_uint2(
        *reinterpret_cast<uint32_t*>(&h01), *reinterpret_cast<uint32_t*>(&h23));
}

// ---------------------------------------------------------------------------
// All 4 weights in ONE launch: W[K,N] fp32 -> transposed blocked fp16 plane.
// ---------------------------------------------------------------------------
__global__ __launch_bounds__(256) void tsplit_kernel(
    const float* __restrict__ W0, const float* __restrict__ W1,
    const float* __restrict__ W2, const float* __restrict__ W3,
    unsigned char* __restrict__ outbase, int K, int N)
{
    __shared__ float t[32][33];
    const int tx = threadIdx.x, ty = threadIdx.y;
    const int bx = blockIdx.x, by = blockIdx.y, z = blockIdx.z;
    const float* W = (z == 0) ? W0 : (z == 1) ? W1 : (z == 2) ? W2 : W3;
    unsigned char* out = outbase + (size_t)z * WONE_BYTES;
#pragma unroll
    for (int j = 0; j < 32; j += 8)
        t[ty + j][tx] = W[(size_t)(by * 32 + ty + j) * N + bx * 32 + tx];
    __syncthreads();
#pragma unroll
    for (int j = 0; j < 32; j += 8) {
        float v = t[tx][ty + j];
        const int n = bx * 32 + ty + j;
        const int k = by * 32 + tx;
        unsigned char* base = out + ((size_t)((n >> 7) * KCq + (k >> 5))) * WBLK
                            + (n & 127) * 80 + (k & 31) * 2;
        *reinterpret_cast<__half*>(base) = __float2half_rn(v);
    }
}

// ---------------------------------------------------------------------------
// Mask permute: fp32 [B,1,T,T] -> bf16, consumer-ordered per (b,qtile,chunk,tid)
// ---------------------------------------------------------------------------
__global__ __launch_bounds__(256) void mask_permute(
    const float* __restrict__ mask, unsigned char* __restrict__ out)
{
    __shared__ float tile[128 * 64];
    const int b = blockIdx.z, qt = blockIdx.y, ch = blockIdx.x;
    const int tid = threadIdx.x;
    const float* src = mask + ((size_t)b * Tq + qt * 128) * Tq + ch * 64;
    for (int i = tid; i < 2048; i += 256) {
        const int row = i >> 4, c4 = (i & 15) * 4;
        float4 v = *reinterpret_cast<const float4*>(src + (size_t)row * Tq + c4);
        tile[row * 64 + c4 + 0] = v.x;
        tile[row * 64 + c4 + 1] = v.y;
        tile[row * 64 + c4 + 2] = v.z;
        tile[row * 64 + c4 + 3] = v.w;
    }
    __syncthreads();
    const int wid = tid >> 5, lane = tid & 31;
    const int r0 = wid * 16 + (lane >> 2);
    const int cb = (lane & 3) * 2;
    uint32_t outv[16];
#pragma unroll
    for (int t = 0; t < 8; ++t)
#pragma unroll
        for (int u = 0; u < 2; ++u) {
            const int row = r0 + u * 8;
            const int c = t * 8 + cb;
            __nv_bfloat162 p = __float22bfloat162_rn(
                make_float2(tile[row * 64 + c], tile[row * 64 + c + 1]));
            outv[t * 2 + u] = *reinterpret_cast<uint32_t*>(&p);
        }
    uint4* dst = reinterpret_cast<uint4*>(
        out + ((size_t)((b * 16 + qt) * 32 + ch)) * MBLK + tid * 64);
#pragma unroll
    for (int i = 0; i < 4; ++i)
        dst[i] = make_uint4(outv[4 * i], outv[4 * i + 1], outv[4 * i + 2], outv[4 * i + 3]);
}

// ---------------------------------------------------------------------------
// bulk-copy GEMM (pure fp16, 4-stage pipeline, GBK=32): C = Ah @ Bh^T.
// ---------------------------------------------------------------------------
#define GBM 128
#define GBN 128
#define GBK 32
#define STAGEB (XBLK + WBLK)              // 20480: A | B
#define GEMM_SMEM (4 * STAGEB + 32)       // 4 stages + 4 mbars

__device__ __forceinline__ void store_qkv(unsigned char* dst, int z, int row, int col,
                                          float v0, float v1) {
    const int b = row >> 11, tok = row & 2047;
    const int h = col >> 6, dh = col & 63;
    size_t off;
    if (z == 0) {
        off = ((size_t)((b * Hq + h) * 16 + (tok >> 7))) * QBLK
            + (size_t)(tok & 127) * 144 + dh * 2;
    } else {
        off = ((size_t)((b * Hq + h) * 32 + (tok >> 6))) * KVBLK
            + (size_t)(tok & 63) * 144 + dh * 2;
    }
    __half2 hh = __float22half2_rn(make_float2(v0, v1));
    *reinterpret_cast<uint32_t*>(dst + off) = *reinterpret_cast<uint32_t*>(&hh);
}

__global__ __launch_bounds__(256, 2) void gemm_bulk_kernel(
    const unsigned char* __restrict__ Aplane, const unsigned char* __restrict__ Wb,
    unsigned char* __restrict__ qb, unsigned char* __restrict__ kp,
    unsigned char* __restrict__ vp,
    float* __restrict__ C, const float* __restrict__ bias,
    int M, int N, int K)
{
    extern __shared__ char smem[];
    const uint32_t sb = smem_u32(smem);
    const uint32_t mbb = sb + 4 * STAGEB;     // 4 mbarriers, 8B apart

    const int tid = threadIdx.x;
    const int wid = tid >> 5;
    const int lane = tid & 31;
    const int warp_m = wid >> 1;
    const int warp_n = wid & 1;
    const int row0 = blockIdx.y * GBM;
    const int col0 = blockIdx.x * GBN;
    const int z = blockIdx.z;
    const int KC = K / GBK;                   // 32

    const unsigned char* Asrc = Aplane + ((size_t)blockIdx.y * KC) * XBLK;
    const unsigned char* Bsrc = (C == nullptr ? Wb + (size_t)z * WONE_BYTES : Wb)
                              + ((size_t)blockIdx.x * KC) * WBLK;

    if (tid == 0) {
#pragma unroll
        for (int s = 0; s < 4; ++s) MBAR_INIT(mbb + 8 * s, 1);
    }
    __syncthreads();

    if (tid == 0) {
#pragma unroll
        for (int s = 0; s < 3; ++s) {
            MBAR_EXPECT_TX(mbb + 8 * s, STAGEB);
            CP_BULK(sb + s * STAGEB, Asrc + (size_t)s * XBLK, XBLK, mbb + 8 * s);
            CP_BULK(sb + s * STAGEB + XBLK, Bsrc + (size_t)s * WBLK, WBLK, mbb + 8 * s);
        }
    }

    float acc[2][8][4];
#pragma unroll
    for (int i = 0; i < 2; ++i)
#pragma unroll
        for (int j = 0; j < 8; ++j)
#pragma unroll
            for (int q = 0; q < 4; ++q) acc[i][j][q] = 0.0f;

    for (int c = 0; c < KC; ++c) {
        if (c + 3 < KC && tid == 0) {
            const int f = c + 3;
            const int s = f & 3;
            MBAR_EXPECT_TX(mbb + 8 * s, STAGEB);
            CP_BULK(sb + s * STAGEB, Asrc + (size_t)f * XBLK, XBLK, mbb + 8 * s);
            CP_BULK(sb + s * STAGEB + XBLK, Bsrc + (size_t)f * WBLK, WBLK, mbb + 8 * s);
        }
        mbar_wait(mbb + 8 * (c & 3), (c >> 2) & 1);

        const uint32_t st = sb + (c & 3) * STAGEB;
        const uint32_t aP = st;
        const uint32_t bP = st + XBLK;

#pragma unroll
        for (int kst = 0; kst < 2; ++kst) {
            const int kb = kst * 32 + (lane >> 4) * 16;

            uint32_t a4[2][4];
#pragma unroll
            for (int mt = 0; mt < 2; ++mt) {
                const int arow = warp_m * 32 + mt * 16 + (lane & 15);
                LDSM_X4(a4[mt][0], a4[mt][1], a4[mt][2], a4[mt][3], aP + arow * 80 + kb);
            }

#pragma unroll
            for (int g = 0; g < 2; ++g) {
                uint32_t b4[4][2];
                const int brow_in = (lane & 7) + ((lane >> 4) << 3);
                const int bkb = kst * 32 + ((lane >> 3) & 1) * 16;
#pragma unroll
                for (int p = 0; p < 2; ++p) {
                    const int nb = warp_n * 64 + g * 32 + p * 16;
                    const uint32_t ba = (nb + brow_in) * 80 + bkb;
                    LDSM_X4(b4[2 * p][0], b4[2 * p][1], b4[2 * p + 1][0], b4[2 * p + 1][1],
                            bP + ba);
                }
#pragma unroll
                for (int mt = 0; mt < 2; ++mt)
#pragma unroll
                    for (int nt = 0; nt < 4; ++nt) {
                        float* cc = acc[mt][g * 4 + nt];
                        MMA_FP16(cc[0], cc[1], cc[2], cc[3],
                                 a4[mt][0], a4[mt][1], a4[mt][2], a4[mt][3],
                                 b4[nt][0], b4[nt][1]);
                    }
            }
        }
        __syncthreads();
    }

    // epilogue
    if (C != nullptr) {
#pragma unroll
        for (int mt = 0; mt < 2; ++mt) {
            const int rbase = row0 + warp_m * 32 + mt * 16 + (lane >> 2);
#pragma unroll
            for (int nt = 0; nt < 8; ++nt) {
                const int cbase = col0 + warp_n * 64 + nt * 8 + (lane & 3) * 2;
                float v0 = acc[mt][nt][0], v1 = acc[mt][nt][1];
                float v2 = acc[mt][nt][2], v3 = acc[mt][nt][3];
                const float b0 = bias[cbase], b1 = bias[cbase + 1];
                v0 += b0; v1 += b1; v2 += b0; v3 += b1;
                *reinterpret_cast<float2*>(C + (size_t)rbase * N + cbase) = make_float2(v0, v1);
                *reinterpret_cast<float2*>(C + (size_t)(rbase + 8) * N + cbase) = make_float2(v2, v3);
            }
        }
    } else {
        const float scale = (z == 0) ? SCALEq : 1.0f;
        unsigned char* dst = (z == 0) ? qb : (z == 1) ? kp : vp;
#pragma unroll
        for (int mt = 0; mt < 2; ++mt) {
            const int rbase = row0 + warp_m * 32 + mt * 16 + (lane >> 2);
#pragma unroll
            for (int nt = 0; nt < 8; ++nt) {
                const int cbase = col0 + warp_n * 64 + nt * 8 + (lane & 3) * 2;
                store_qkv(dst, z, rbase, cbase,
                          acc[mt][nt][0] * scale, acc[mt][nt][1] * scale);
                store_qkv(dst, z, rbase + 8, cbase,
                          acc[mt][nt][2] * scale, acc[mt][nt][3] * scale);
            }
        }
    }
}

// ---------------------------------------------------------------------------
// Tensor-core flash attention, pure fp16, 4-stage KV pipeline.
// R13 exp-domain softmax + mask register prefetch ahead of the S-MMA chain.
// ---------------------------------------------------------------------------
#define FBQ 128
#define FBK 64
#define FROWB 144
#define FQ_TILE (FBQ * FROWB)               // 18432
#define FKV_TILE (FBK * FROWB)              // 9216
#define F_ST FQ_TILE                        // 18432
#define F_STAGE (2 * FKV_TILE)              // 18432 (K | V)
#define FLASH_SMEM (F_ST + 4 * F_STAGE + 64)

__global__ __launch_bounds__(256, 2) void flash_mma_kernel(
    const unsigned char* __restrict__ maskp,
    const unsigned char* __restrict__ qb,
    const unsigned char* __restrict__ kp,
    const unsigned char* __restrict__ vp,
    unsigned char* __restrict__ ap)
{
    extern __shared__ char smem[];
    const uint32_t sb = smem_u32(smem);
    const uint32_t mbQ = sb + F_ST + 4 * F_STAGE;
    const uint32_t mbb = mbQ + 8;            // 4 KV mbarriers

    const int tid  = threadIdx.x;
    const int wid  = tid >> 5;
    const int lane = tid & 31;
    const int qt = blockIdx.x;
    const int h  = blockIdx.y;
    const int b  = blockIdx.z;

    const unsigned char* qsrc = qb + ((size_t)((b * Hq + h) * 16 + qt)) * QBLK;
    const unsigned char* kbase = kp + ((size_t)((b * Hq + h) * 32)) * KVBLK;
    const unsigned char* vbase = vp + ((size_t)((b * Hq + h) * 32)) * KVBLK;
    const unsigned char* mbase = maskp + ((size_t)((b * 16 + qt) * 32)) * MBLK + tid * 64;

    if (tid == 0) {
        MBAR_INIT(mbQ, 1);
#pragma unroll
        for (int s = 0; s < 4; ++s) MBAR_INIT(mbb + 8 * s, 1);
    }
    __syncthreads();

    if (tid == 0) {
        MBAR_EXPECT_TX(mbQ, FQ_TILE);
        CP_BULK(sb, qsrc, FQ_TILE, mbQ);
#pragma unroll
        for (int s = 0; s < 3; ++s) {
            MBAR_EXPECT_TX(mbb + 8 * s, F_STAGE);
            CP_BULK(sb + F_ST + s * F_STAGE, kbase + (size_t)s * KVBLK, KVBLK, mbb + 8 * s);
            CP_BULK(sb + F_ST + s * F_STAGE + FKV_TILE, vbase + (size_t)s * KVBLK, KVBLK,
                    mbb + 8 * s);
        }
    }

    float o[8][4];
#pragma unroll
    for (int t = 0; t < 8; ++t)
#pragma unroll
        for (int j = 0; j < 4; ++j) o[t][j] = 0.0f;
    float m0 = -1e30f, m1 = -1e30f, l0 = 0.0f, l1 = 0.0f;

    const int r0g = qt * FBQ + wid * 16 + (lane >> 2);
    const int quadcol = (lane & 3) * 2;

    mbar_wait(mbQ, 0);

    const int chunks = Tq / FBK;   // 32
    for (int c = 0; c < chunks; ++c) {
        if (c + 3 < chunks && tid == 0) {
            const int f = c + 3;
            const int s = f & 3;
            MBAR_EXPECT_TX(mbb + 8 * s, F_STAGE);
            CP_BULK(sb + F_ST + s * F_STAGE, kbase + (size_t)f * KVBLK, KVBLK, mbb + 8 * s);
            CP_BULK(sb + F_ST + s * F_STAGE + FKV_TILE, vbase + (size_t)f * KVBLK, KVBLK,
                    mbb + 8 * s);
        }
        mbar_wait(mbb + 8 * (c & 3), (c >> 2) & 1);

        const uint32_t st = sb + F_ST + (c & 3) * F_STAGE;
        const uint32_t kP = st;
        const uint32_t vP = st + FKV_TILE;

        // ---- mask prefetch: issue LDGs now, consume after the MMA chain ----
        uint4 mq0, mq1, mq2, mq3;
        {
            const uint4* mp = reinterpret_cast<const uint4*>(mbase + (size_t)c * MBLK);
            mq0 = mp[0]; mq1 = mp[1]; mq2 = mp[2]; mq3 = mp[3];
        }

        // ---- S = Q @ K^T (fp16, 1 pass) ----
        float s[8][4];
#pragma unroll
        for (int t = 0; t < 8; ++t)
#pragma unroll
            for (int j = 0; j < 4; ++j) s[t][j] = 0.0f;

        const int brow_in = (lane & 7) + ((lane >> 4) << 3);
#pragma unroll
        for (int kk = 0; kk < 4; ++kk) {
            uint32_t q4[4];
            const uint32_t qa = sb + (wid * 16 + (lane & 15)) * FROWB
                              + kk * 32 + (lane >> 4) * 16;
            LDSM_X4(q4[0], q4[1], q4[2], q4[3], qa);

            const int bkb = kk * 32 + ((lane >> 3) & 1) * 16;
#pragma unroll
            for (int p = 0; p < 4; ++p) {
                uint32_t b4[2][2];
                const uint32_t ba = (p * 16 + brow_in) * FROWB + bkb;
                LDSM_X4(b4[0][0], b4[0][1], b4[1][0], b4[1][1], kP + ba);
#pragma unroll
                for (int u = 0; u < 2; ++u) {
                    float* cc = s[2 * p + u];
                    MMA_FP16(cc[0], cc[1], cc[2], cc[3],
                             q4[0], q4[1], q4[2], q4[3], b4[u][0], b4[u][1]);
                }
            }
        }

        // ---- mask add (prefetched) + online softmax ----
        {
            uint32_t mu[16];
            mu[0]  = mq0.x; mu[1]  = mq0.y; mu[2]  = mq0.z; mu[3]  = mq0.w;
            mu[4]  = mq1.x; mu[5]  = mq1.y; mu[6]  = mq1.z; mu[7]  = mq1.w;
            mu[8]  = mq2.x; mu[9]  = mq2.y; mu[10] = mq2.z; mu[11] = mq2.w;
            mu[12] = mq3.x; mu[13] = mq3.y; mu[14] = mq3.z; mu[15] = mq3.w;
#pragma unroll
            for (int t = 0; t < 8; ++t) {
                float2 lo2 = __bfloat1622float2(
                    *reinterpret_cast<__nv_bfloat162*>(&mu[2 * t]));
                float2 hi2 = __bfloat1622float2(
                    *reinterpret_cast<__nv_bfloat162*>(&mu[2 * t + 1]));
                s[t][0] += lo2.x; s[t][1] += lo2.y;
                s[t][2] += hi2.x; s[t][3] += hi2.y;
            }
        }

        float mx0 = -1e30f, mx1 = -1e30f;
#pragma unroll
        for (int t = 0; t < 8; ++t) {
            mx0 = fmaxf(mx0, fmaxf(s[t][0], s[t][1]));
            mx1 = fmaxf(mx1, fmaxf(s[t][2], s[t][3]));
        }
        mx0 = fmaxf(mx0, __shfl_xor_sync(0xffffffffu, mx0, 1));
        mx0 = fmaxf(mx0, __shfl_xor_sync(0xffffffffu, mx0, 2));
        mx1 = fmaxf(mx1, __shfl_xor_sync(0xffffffffu, mx1, 1));
        mx1 = fmaxf(mx1, __shfl_xor_sync(0xffffffffu, mx1, 2));

        const float mn0 = fmaxf(m0, mx0);
        const float mn1 = fmaxf(m1, mx1);
        const float a0 = __expf(m0 - mn0);
        const float a1 = __expf(m1 - mn1);
        m0 = mn0; m1 = mn1;

        float sum0 = 0.0f, sum1 = 0.0f;
#pragma unroll
        for (int t = 0; t < 8; ++t) {
            s[t][0] = __expf(s[t][0] - mn0);
            s[t][1] = __expf(s[t][1] - mn0);
            s[t][2] = __expf(s[t][2] - mn1);
            s[t][3] = __expf(s[t][3] - mn1);
            sum0 += s[t][0] + s[t][1];
            sum1 += s[t][2] + s[t][3];
        }
        sum0 += __shfl_xor_sync(0xffffffffu, sum0, 1);
        sum0 += __shfl_xor_sync(0xffffffffu, sum0, 2);
        sum1 += __shfl_xor_sync(0xffffffffu, sum1, 1);
        sum1 += __shfl_xor_sync(0xffffffffu, sum1, 2);
        l0 = l0 * a0 + sum0;
        l1 = l1 * a1 + sum1;

#pragma unroll
        for (int t = 0; t < 8; ++t) {
            o[t][0] *= a0; o[t][1] *= a0;
            o[t][2] *= a1; o[t][3] *= a1;
        }

        // ---- P fragments (fp16) ----
        uint32_t pH[4][4];
#pragma unroll
        for (int j = 0; j < 4; ++j) {
#pragma unroll
            for (int u = 0; u < 2; ++u) {
#pragma unroll
                for (int w = 0; w < 2; ++w) {
                    __half2 hh = __float22half2_rn(make_float2(
                        s[2 * j + w][2 * u + 0], s[2 * j + w][2 * u + 1]));
                    pH[j][2 * w + u] = *reinterpret_cast<uint32_t*>(&hh);
                }
            }
        }

        // ---- O += P @ V (fp16, 1 pass) ----
#pragma unroll
        for (int j = 0; j < 4; ++j) {
#pragma unroll
            for (int p = 0; p < 4; ++p) {
                uint32_t v4[2][2];
                const uint32_t va = (j * 16 + (lane & 15)) * FROWB
                                  + p * 32 + (lane >> 4) * 16;
                LDSM_X4_T(v4[0][0], v4[0][1], v4[1][0], v4[1][1], vP + va);
#pragma unroll
                for (int u = 0; u < 2; ++u) {
                    float* cc = o[2 * p + u];
                    MMA_FP16(cc[0], cc[1], cc[2], cc[3],
                             pH[j][0], pH[j][1], pH[j][2], pH[j][3],
                             v4[u][0], v4[u][1]);
                }
            }
        }
        __syncthreads();
    }

    // ---- epilogue: normalize, write blocked single fp16 plane A ----
    const float inv0 = 1.0f / l0;
    const float inv1 = 1.0f / l1;
    const int grow = b * Tq + r0g;
#pragma unroll
    for (int t = 0; t < 8; ++t) {
        const int col = h * DHq + t * 8 + quadcol;
        {
            unsigned char* base = ap
                + ((size_t)((grow >> 7) * KCq + (col >> 5))) * XBLK
                + (grow & 127) * 80 + (col & 31) * 2;
            __half2 hh = __float22half2_rn(make_float2(o[t][0] * inv0, o[t][1] * inv0));
            *reinterpret_cast<uint32_t*>(base) = *reinterpret_cast<uint32_t*>(&hh);
        }
        {
            const int grow2 = grow + 8;
            unsigned char* base = ap
                + ((size_t)((grow2 >> 7) * KCq + (col >> 5))) * XBLK
                + (grow2 & 127) * 80 + (col & 31) * 2;
            __half2 hh = __float22half2_rn(make_float2(o[t][2] * inv1, o[t][3] * inv1));
            *reinterpret_cast<uint32_t*>(base) = *reinterpret_cast<uint32_t*>(&hh);
        }
    }
}

// ---------------------------------------------------------------------------
// kernel_launch
// Inputs: x, attention_mask, Wq, Wk, Wv, Wo, bo
// ---------------------------------------------------------------------------
extern "C" void kernel_launch(void* const* d_in, const int* in_sizes, int n_in,
                              void* d_out, int out_size)
{
    (void)in_sizes; (void)n_in; (void)out_size;
    const float* x    = (const float*)d_in[0];
    const float* mask = (const float*)d_in[1];
    const float* Wq   = (const float*)d_in[2];
    const float* Wk   = (const float*)d_in[3];
    const float* Wv   = (const float*)d_in[4];
    const float* Wo   = (const float*)d_in[5];
    const float* bo   = (const float*)d_in[6];
    float* out = (float*)d_out;

    unsigned char *xp, *ap, *w, *qb, *kpb, *vpb, *maskp;
    cudaGetSymbolAddress((void**)&xp, g_xp);
    cudaGetSymbolAddress((void**)&ap, g_ap);
    cudaGetSymbolAddress((void**)&w, g_w);
    cudaGetSymbolAddress((void**)&qb, g_qb);
    cudaGetSymbolAddress((void**)&kpb, g_kp);
    cudaGetSymbolAddress((void**)&vpb, g_vp);
    cudaGetSymbolAddress((void**)&maskp, g_maskp);

    const int M = Bq * Tq;     // 8192
    const int N = INNERq;      // 1024
    const int K = Dq;          // 1024
    const int nx = M * K;

    // Side stream: tsplit (weights) first, then mask permute.
    // Fork/join via events is graph-capturable; objects created once outside capture.
    static cudaStream_t s2 = nullptr;
    static cudaEvent_t evFork = nullptr, evW = nullptr, evM = nullptr;
    if (s2 == nullptr) {
        cudaStreamCreateWithFlags(&s2, cudaStreamNonBlocking);
        cudaEventCreateWithFlags(&evFork, cudaEventDisableTiming);
        cudaEventCreateWithFlags(&evW, cudaEventDisableTiming);
        cudaEventCreateWithFlags(&evM, cudaEventDisableTiming);
    }

    cudaEventRecord(evFork, 0);
    cudaStreamWaitEvent(s2, evFork, 0);
    dim3 tGrid(N / 32, K / 32, 4), tBlk(32, 8);
    tsplit_kernel<<<tGrid, tBlk, 0, s2>>>(Wq, Wk, Wv, Wo, w, K, N);
    cudaEventRecord(evW, s2);
    dim3 mGrid(32, 16, Bq);
    mask_permute<<<mGrid, 256, 0, s2>>>(mask, maskp);
    cudaEventRecord(evM, s2);

    // main chain: x conversion (runs concurrently with tsplit/mask)
    split_kernel<<<nx / (256 * 4), 256>>>(x, xp);

    // join: QKV GEMM needs weights
    cudaStreamWaitEvent(0, evW, 0);

    // Q,K,V projections (one launch, 4-stage bulk pipeline, pure fp16)
    cudaFuncSetAttribute(gemm_bulk_kernel,
                         cudaFuncAttributeMaxDynamicSharedMemorySize, GEMM_SMEM);
    dim3 qkvGrid(N / GBN, M / GBM, 3);
    gemm_bulk_kernel<<<qkvGrid, 256, GEMM_SMEM>>>(xp, w, qb, kpb, vpb,
                                                  nullptr, nullptr, M, N, K);

    // join: flash needs the permuted mask
    cudaStreamWaitEvent(0, evM, 0);

    // flash attention (pure fp16, 4-stage KV pipeline)
    cudaFuncSetAttribute(flash_mma_kernel,
                         cudaFuncAttributeMaxDynamicSharedMemorySize, FLASH_SMEM);
    dim3 fGrid(Tq / FBQ, Hq, Bq);
    flash_mma_kernel<<<fGrid, 256, FLASH_SMEM>>>(maskp, qb, kpb, vpb, ap);

    // output projection (fp32 + bias, pure fp16)
    dim3 oGrid(N / GBN, M / GBM, 1);
    gemm_bulk_kernel<<<oGrid, 256, GEMM_SMEM>>>(ap, w + 3 * WONE_BYTES,
                                                nullptr, nullptr, nullptr,
                                                out, bo, M, Dq, INNERq);
}

// round 16
// speedup vs baseline: 1.1079x; 1.0834x over previous
#include <cuda_runtime.h>
#include <cuda_bf16.h>
#include <cuda_fp16.h>
#include <cstdint>
#include <cstddef>

// ---------------------------------------------------------------------------
// Problem constants
// ---------------------------------------------------------------------------
#define Bq   4
#define Tq   2048
#define Dq   1024
#define Hq   16
#define DHq  64
#define INNERq 1024
#define SCALEq 0.125f     // 64^-0.5

// Blocked-layout sizes (all single fp16 planes)
#define KCq 32
#define XBLK 10240
#define WBLK 10240
#define WONE_BYTES ((size_t)8 * 32 * WBLK)
#define XPLANE_BYTES ((size_t)64 * 32 * XBLK)
#define QBLK 18432
#define KVBLK 9216
#define QB_BYTES ((size_t)Bq * Hq * 16 * QBLK)
#define KP_BYTES ((size_t)Bq * Hq * 32 * KVBLK)
#define MBLK 16384
#define MP_BYTES ((size_t)Bq * 16 * 32 * MBLK)

// ---------------------------------------------------------------------------
// Scratch (device globals; allocation is forbidden)
// ---------------------------------------------------------------------------
__device__ __align__(128) unsigned char g_xp[XPLANE_BYTES];
__device__ __align__(128) unsigned char g_ap[XPLANE_BYTES];
__device__ __align__(128) unsigned char g_w[4 * WONE_BYTES];
__device__ __align__(128) unsigned char g_qb[QB_BYTES];
__device__ __align__(128) unsigned char g_kp[KP_BYTES];
__device__ __align__(128) unsigned char g_vp[KP_BYTES];
__device__ __align__(128) unsigned char g_maskp[MP_BYTES];

// ---------------------------------------------------------------------------
// PTX helpers
// ---------------------------------------------------------------------------
__device__ __forceinline__ uint32_t smem_u32(const void* p) {
    uint32_t a;
    asm("{ .reg .u64 t; cvta.to.shared.u64 t, %1; cvt.u32.u64 %0, t; }" : "=r"(a) : "l"(p));
    return a;
}

#define MBAR_INIT(mbar, cnt) \
    asm volatile("mbarrier.init.shared.b64 [%0], %1;" :: "r"((uint32_t)(mbar)), "r"((uint32_t)(cnt)) : "memory")
#define MBAR_EXPECT_TX(mbar, bytes) \
    asm volatile("mbarrier.arrive.expect_tx.shared.b64 _, [%0], %1;" \
                 :: "r"((uint32_t)(mbar)), "r"((uint32_t)(bytes)) : "memory")
#define MBAR_ARRIVE(mbar) \
    asm volatile("mbarrier.arrive.shared.b64 _, [%0];" :: "r"((uint32_t)(mbar)) : "memory")
#define CP_BULK(smem_dst, gsrc, bytes, mbar) \
    asm volatile("cp.async.bulk.shared::cluster.global.mbarrier::complete_tx::bytes [%0], [%1], %2, [%3];" \
                 :: "r"((uint32_t)(smem_dst)), "l"(gsrc), "r"((uint32_t)(bytes)), \
                    "r"((uint32_t)(mbar)) : "memory")

__device__ __forceinline__ void mbar_wait(uint32_t mbar, uint32_t parity) {
    asm volatile(
        "{\n\t.reg .pred P;\n\t"
        "WAIT_%=:\n\t"
        "mbarrier.try_wait.parity.acquire.cta.shared::cta.b64 P, [%0], %1, 0x989680;\n\t"
        "@P bra DONE_%=;\n\t"
        "bra WAIT_%=;\n\t"
        "DONE_%=:\n\t}"
        :: "r"(mbar), "r"(parity) : "memory");
}

#define LDSM_X4(r0, r1, r2, r3, addr) \
    asm volatile("ldmatrix.sync.aligned.m8n8.x4.shared.b16 {%0,%1,%2,%3}, [%4];" \
                 : "=r"(r0), "=r"(r1), "=r"(r2), "=r"(r3) : "r"(addr))

#define LDSM_X4_T(r0, r1, r2, r3, addr) \
    asm volatile("ldmatrix.sync.aligned.m8n8.x4.trans.shared.b16 {%0,%1,%2,%3}, [%4];" \
                 : "=r"(r0), "=r"(r1), "=r"(r2), "=r"(r3) : "r"(addr))

#define MMA_FP16(c0, c1, c2, c3, a0, a1, a2, a3, b0, b1) \
    asm volatile("mma.sync.aligned.m16n8k16.row.col.f32.f16.f16.f32 " \
                 "{%0,%1,%2,%3}, {%4,%5,%6,%7}, {%8,%9}, {%0,%1,%2,%3};" \
                 : "+f"(c0), "+f"(c1), "+f"(c2), "+f"(c3) \
                 : "r"(a0), "r"(a1), "r"(a2), "r"(a3), "r"(b0), "r"(b1))

// ---------------------------------------------------------------------------
// x[8192,1024] fp32 -> blocked single fp16 plane
// ---------------------------------------------------------------------------
__global__ __launch_bounds__(256) void split_kernel(
    const float* __restrict__ in, unsigned char* __restrict__ out)
{
    const int i = (blockIdx.x * 256 + threadIdx.x) * 4;
    float4 v = *reinterpret_cast<const float4*>(in + i);
    const int row = i >> 10, col = i & 1023;
    unsigned char* base = out + ((size_t)((row >> 7) * KCq + (col >> 5))) * XBLK
                        + (row & 127) * 80 + (col & 31) * 2;
    __half2 h01 = __float22half2_rn(make_float2(v.x, v.y));
    __half2 h23 = __float22half2_rn(make_float2(v.z, v.w));
    *reinterpret_cast<uint2*>(base) = make_uint2(
        *reinterpret_cast<uint32_t*>(&h01), *reinterpret_cast<uint32_t*>(&h23));
}

// ---------------------------------------------------------------------------
// All 4 weights in ONE launch: W[K,N] fp32 -> transposed blocked fp16 plane.
// ---------------------------------------------------------------------------
__global__ __launch_bounds__(256) void tsplit_kernel(
    const float* __restrict__ W0, const float* __restrict__ W1,
    const float* __restrict__ W2, const float* __restrict__ W3,
    unsigned char* __restrict__ outbase, int K, int N)
{
    __shared__ float t[32][33];
    const int tx = threadIdx.x, ty = threadIdx.y;
    const int bx = blockIdx.x, by = blockIdx.y, z = blockIdx.z;
    const float* W = (z == 0) ? W0 : (z == 1) ? W1 : (z == 2) ? W2 : W3;
    unsigned char* out = outbase + (size_t)z * WONE_BYTES;
#pragma unroll
    for (int j = 0; j < 32; j += 8)
        t[ty + j][tx] = W[(size_t)(by * 32 + ty + j) * N + bx * 32 + tx];
    __syncthreads();
#pragma unroll
    for (int j = 0; j < 32; j += 8) {
        float v = t[tx][ty + j];
        const int n = bx * 32 + ty + j;
        const int k = by * 32 + tx;
        unsigned char* base = out + ((size_t)((n >> 7) * KCq + (k >> 5))) * WBLK
                            + (n & 127) * 80 + (k & 31) * 2;
        *reinterpret_cast<__half*>(base) = __float2half_rn(v);
    }
}

// ---------------------------------------------------------------------------
// Mask permute: fp32 [B,1,T,T] -> bf16, consumer-ordered per (b,qtile,chunk,tid)
// ---------------------------------------------------------------------------
__global__ __launch_bounds__(256) void mask_permute(
    const float* __restrict__ mask, unsigned char* __restrict__ out)
{
    __shared__ float tile[128 * 64];
    const int b = blockIdx.z, qt = blockIdx.y, ch = blockIdx.x;
    const int tid = threadIdx.x;
    const float* src = mask + ((size_t)b * Tq + qt * 128) * Tq + ch * 64;
    for (int i = tid; i < 2048; i += 256) {
        const int row = i >> 4, c4 = (i & 15) * 4;
        float4 v = *reinterpret_cast<const float4*>(src + (size_t)row * Tq + c4);
        tile[row * 64 + c4 + 0] = v.x;
        tile[row * 64 + c4 + 1] = v.y;
        tile[row * 64 + c4 + 2] = v.z;
        tile[row * 64 + c4 + 3] = v.w;
    }
    __syncthreads();
    const int wid = tid >> 5, lane = tid & 31;
    const int r0 = wid * 16 + (lane >> 2);
    const int cb = (lane & 3) * 2;
    uint32_t outv[16];
#pragma unroll
    for (int t = 0; t < 8; ++t)
#pragma unroll
        for (int u = 0; u < 2; ++u) {
            const int row = r0 + u * 8;
            const int c = t * 8 + cb;
            __nv_bfloat162 p = __float22bfloat162_rn(
                make_float2(tile[row * 64 + c], tile[row * 64 + c + 1]));
            outv[t * 2 + u] = *reinterpret_cast<uint32_t*>(&p);
        }
    uint4* dst = reinterpret_cast<uint4*>(
        out + ((size_t)((b * 16 + qt) * 32 + ch)) * MBLK + tid * 64);
#pragma unroll
    for (int i = 0; i < 4; ++i)
        dst[i] = make_uint4(outv[4 * i], outv[4 * i + 1], outv[4 * i + 2], outv[4 * i + 3]);
}

// ---------------------------------------------------------------------------
// bulk-copy GEMM (pure fp16, 4-stage producer/consumer pipeline, GBK=32).
// No per-chunk __syncthreads: consumers arrive on empty[] mbarriers.
// ---------------------------------------------------------------------------
#define GBM 128
#define GBN 128
#define GBK 32
#define STAGEB (XBLK + WBLK)              // 20480: A | B
#define GEMM_SMEM (4 * STAGEB + 64)       // 4 stages + 4 full + 4 empty mbars

__device__ __forceinline__ void store_qkv(unsigned char* dst, int z, int row, int col,
                                          float v0, float v1) {
    const int b = row >> 11, tok = row & 2047;
    const int h = col >> 6, dh = col & 63;
    size_t off;
    if (z == 0) {
        off = ((size_t)((b * Hq + h) * 16 + (tok >> 7))) * QBLK
            + (size_t)(tok & 127) * 144 + dh * 2;
    } else {
        off = ((size_t)((b * Hq + h) * 32 + (tok >> 6))) * KVBLK
            + (size_t)(tok & 63) * 144 + dh * 2;
    }
    __half2 hh = __float22half2_rn(make_float2(v0, v1));
    *reinterpret_cast<uint32_t*>(dst + off) = *reinterpret_cast<uint32_t*>(&hh);
}

__global__ __launch_bounds__(256, 2) void gemm_bulk_kernel(
    const unsigned char* __restrict__ Aplane, const unsigned char* __restrict__ Wb,
    unsigned char* __restrict__ qb, unsigned char* __restrict__ kp,
    unsigned char* __restrict__ vp,
    float* __restrict__ C, const float* __restrict__ bias,
    int M, int N, int K)
{
    extern __shared__ char smem[];
    const uint32_t sb = smem_u32(smem);
    const uint32_t mbF = sb + 4 * STAGEB;      // full barriers (count 1 + tx)
    const uint32_t mbE = mbF + 32;             // empty barriers (count 8)

    const int tid = threadIdx.x;
    const int wid = tid >> 5;
    const int lane = tid & 31;
    const int warp_m = wid >> 1;
    const int warp_n = wid & 1;
    const int row0 = blockIdx.y * GBM;
    const int col0 = blockIdx.x * GBN;
    const int z = blockIdx.z;
    const int KC = K / GBK;                    // 32

    const unsigned char* Asrc = Aplane + ((size_t)blockIdx.y * KC) * XBLK;
    const unsigned char* Bsrc = (C == nullptr ? Wb + (size_t)z * WONE_BYTES : Wb)
                              + ((size_t)blockIdx.x * KC) * WBLK;

    if (tid == 0) {
#pragma unroll
        for (int s = 0; s < 4; ++s) {
            MBAR_INIT(mbF + 8 * s, 1);
            MBAR_INIT(mbE + 8 * s, 8);
        }
    }
    __syncthreads();

    if (tid == 0) {
#pragma unroll
        for (int s = 0; s < 3; ++s) {
            MBAR_EXPECT_TX(mbF + 8 * s, STAGEB);
            CP_BULK(sb + s * STAGEB, Asrc + (size_t)s * XBLK, XBLK, mbF + 8 * s);
            CP_BULK(sb + s * STAGEB + XBLK, Bsrc + (size_t)s * WBLK, WBLK, mbF + 8 * s);
        }
    }

    float acc[2][8][4];
#pragma unroll
    for (int i = 0; i < 2; ++i)
#pragma unroll
        for (int j = 0; j < 8; ++j)
#pragma unroll
            for (int q = 0; q < 4; ++q) acc[i][j][q] = 0.0f;

    for (int c = 0; c < KC; ++c) {
        if (c + 3 < KC && tid == 0) {
            const int f = c + 3;
            const int s = f & 3;
            if (f >= 4) mbar_wait(mbE + 8 * s, ((f >> 2) - 1) & 1);
            MBAR_EXPECT_TX(mbF + 8 * s, STAGEB);
            CP_BULK(sb + s * STAGEB, Asrc + (size_t)f * XBLK, XBLK, mbF + 8 * s);
            CP_BULK(sb + s * STAGEB + XBLK, Bsrc + (size_t)f * WBLK, WBLK, mbF + 8 * s);
        }
        mbar_wait(mbF + 8 * (c & 3), (c >> 2) & 1);

        const uint32_t st = sb + (c & 3) * STAGEB;
        const uint32_t aP = st;
        const uint32_t bP = st + XBLK;

#pragma unroll
        for (int kst = 0; kst < 2; ++kst) {
            const int kb = kst * 32 + (lane >> 4) * 16;

            uint32_t a4[2][4];
#pragma unroll
            for (int mt = 0; mt < 2; ++mt) {
                const int arow = warp_m * 32 + mt * 16 + (lane & 15);
                LDSM_X4(a4[mt][0], a4[mt][1], a4[mt][2], a4[mt][3], aP + arow * 80 + kb);
            }

#pragma unroll
            for (int g = 0; g < 2; ++g) {
                uint32_t b4[4][2];
                const int brow_in = (lane & 7) + ((lane >> 4) << 3);
                const int bkb = kst * 32 + ((lane >> 3) & 1) * 16;
#pragma unroll
                for (int p = 0; p < 2; ++p) {
                    const int nb = warp_n * 64 + g * 32 + p * 16;
                    const uint32_t ba = (nb + brow_in) * 80 + bkb;
                    LDSM_X4(b4[2 * p][0], b4[2 * p][1], b4[2 * p + 1][0], b4[2 * p + 1][1],
                            bP + ba);
                }
#pragma unroll
                for (int mt = 0; mt < 2; ++mt)
#pragma unroll
                    for (int nt = 0; nt < 4; ++nt) {
                        float* cc = acc[mt][g * 4 + nt];
                        MMA_FP16(cc[0], cc[1], cc[2], cc[3],
                                 a4[mt][0], a4[mt][1], a4[mt][2], a4[mt][3],
                                 b4[nt][0], b4[nt][1]);
                    }
            }
        }
        // consumer release: this warp is done reading stage c&3
        if (lane == 0) MBAR_ARRIVE(mbE + 8 * (c & 3));
    }

    // epilogue
    if (C != nullptr) {
#pragma unroll
        for (int mt = 0; mt < 2; ++mt) {
            const int rbase = row0 + warp_m * 32 + mt * 16 + (lane >> 2);
#pragma unroll
            for (int nt = 0; nt < 8; ++nt) {
                const int cbase = col0 + warp_n * 64 + nt * 8 + (lane & 3) * 2;
                float v0 = acc[mt][nt][0], v1 = acc[mt][nt][1];
                float v2 = acc[mt][nt][2], v3 = acc[mt][nt][3];
                const float b0 = bias[cbase], b1 = bias[cbase + 1];
                v0 += b0; v1 += b1; v2 += b0; v3 += b1;
                *reinterpret_cast<float2*>(C + (size_t)rbase * N + cbase) = make_float2(v0, v1);
                *reinterpret_cast<float2*>(C + (size_t)(rbase + 8) * N + cbase) = make_float2(v2, v3);
            }
        }
    } else {
        const float scale = (z == 0) ? SCALEq : 1.0f;
        unsigned char* dst = (z == 0) ? qb : (z == 1) ? kp : vp;
#pragma unroll
        for (int mt = 0; mt < 2; ++mt) {
            const int rbase = row0 + warp_m * 32 + mt * 16 + (lane >> 2);
#pragma unroll
            for (int nt = 0; nt < 8; ++nt) {
                const int cbase = col0 + warp_n * 64 + nt * 8 + (lane & 3) * 2;
                store_qkv(dst, z, rbase, cbase,
                          acc[mt][nt][0] * scale, acc[mt][nt][1] * scale);
                store_qkv(dst, z, rbase + 8, cbase,
                          acc[mt][nt][2] * scale, acc[mt][nt][3] * scale);
            }
        }
    }
}

// ---------------------------------------------------------------------------
// Tensor-core flash attention, pure fp16, 4-stage producer/consumer KV ring.
// No per-chunk __syncthreads.
// ---------------------------------------------------------------------------
#define FBQ 128
#define FBK 64
#define FROWB 144
#define FQ_TILE (FBQ * FROWB)               // 18432
#define FKV_TILE (FBK * FROWB)              // 9216
#define F_ST FQ_TILE                        // 18432
#define F_STAGE (2 * FKV_TILE)              // 18432 (K | V)
#define FLASH_SMEM (F_ST + 4 * F_STAGE + 96)

__global__ __launch_bounds__(256, 2) void flash_mma_kernel(
    const unsigned char* __restrict__ maskp,
    const unsigned char* __restrict__ qb,
    const unsigned char* __restrict__ kp,
    const unsigned char* __restrict__ vp,
    unsigned char* __restrict__ ap)
{
    extern __shared__ char smem[];
    const uint32_t sb = smem_u32(smem);
    const uint32_t mbQ = sb + F_ST + 4 * F_STAGE;
    const uint32_t mbF = mbQ + 8;            // 4 KV full barriers
    const uint32_t mbE = mbF + 32;           // 4 KV empty barriers (count 8)

    const int tid  = threadIdx.x;
    const int wid  = tid >> 5;
    const int lane = tid & 31;
    const int qt = blockIdx.x;
    const int h  = blockIdx.y;
    const int b  = blockIdx.z;

    const unsigned char* qsrc = qb + ((size_t)((b * Hq + h) * 16 + qt)) * QBLK;
    const unsigned char* kbase = kp + ((size_t)((b * Hq + h) * 32)) * KVBLK;
    const unsigned char* vbase = vp + ((size_t)((b * Hq + h) * 32)) * KVBLK;
    const unsigned char* mbase = maskp + ((size_t)((b * 16 + qt) * 32)) * MBLK + tid * 64;

    if (tid == 0) {
        MBAR_INIT(mbQ, 1);
#pragma unroll
        for (int s = 0; s < 4; ++s) {
            MBAR_INIT(mbF + 8 * s, 1);
            MBAR_INIT(mbE + 8 * s, 8);
        }
    }
    __syncthreads();

    if (tid == 0) {
        MBAR_EXPECT_TX(mbQ, FQ_TILE);
        CP_BULK(sb, qsrc, FQ_TILE, mbQ);
#pragma unroll
        for (int s = 0; s < 3; ++s) {
            MBAR_EXPECT_TX(mbF + 8 * s, F_STAGE);
            CP_BULK(sb + F_ST + s * F_STAGE, kbase + (size_t)s * KVBLK, KVBLK, mbF + 8 * s);
            CP_BULK(sb + F_ST + s * F_STAGE + FKV_TILE, vbase + (size_t)s * KVBLK, KVBLK,
                    mbF + 8 * s);
        }
    }

    float o[8][4];
#pragma unroll
    for (int t = 0; t < 8; ++t)
#pragma unroll
        for (int j = 0; j < 4; ++j) o[t][j] = 0.0f;
    float m0 = -1e30f, m1 = -1e30f, l0 = 0.0f, l1 = 0.0f;

    const int r0g = qt * FBQ + wid * 16 + (lane >> 2);
    const int quadcol = (lane & 3) * 2;

    mbar_wait(mbQ, 0);

    const int chunks = Tq / FBK;   // 32
    for (int c = 0; c < chunks; ++c) {
        if (c + 3 < chunks && tid == 0) {
            const int f = c + 3;
            const int s = f & 3;
            if (f >= 4) mbar_wait(mbE + 8 * s, ((f >> 2) - 1) & 1);
            MBAR_EXPECT_TX(mbF + 8 * s, F_STAGE);
            CP_BULK(sb + F_ST + s * F_STAGE, kbase + (size_t)f * KVBLK, KVBLK, mbF + 8 * s);
            CP_BULK(sb + F_ST + s * F_STAGE + FKV_TILE, vbase + (size_t)f * KVBLK, KVBLK,
                    mbF + 8 * s);
        }
        mbar_wait(mbF + 8 * (c & 3), (c >> 2) & 1);

        const uint32_t st = sb + F_ST + (c & 3) * F_STAGE;
        const uint32_t kP = st;
        const uint32_t vP = st + FKV_TILE;

        // ---- mask prefetch: issue LDGs now, consume after the MMA chain ----
        uint4 mq0, mq1, mq2, mq3;
        {
            const uint4* mp = reinterpret_cast<const uint4*>(mbase + (size_t)c * MBLK);
            mq0 = mp[0]; mq1 = mp[1]; mq2 = mp[2]; mq3 = mp[3];
        }

        // ---- S = Q @ K^T (fp16, 1 pass) ----
        float s[8][4];
#pragma unroll
        for (int t = 0; t < 8; ++t)
#pragma unroll
            for (int j = 0; j < 4; ++j) s[t][j] = 0.0f;

        const int brow_in = (lane & 7) + ((lane >> 4) << 3);
#pragma unroll
        for (int kk = 0; kk < 4; ++kk) {
            uint32_t q4[4];
            const uint32_t qa = sb + (wid * 16 + (lane & 15)) * FROWB
                              + kk * 32 + (lane >> 4) * 16;
            LDSM_X4(q4[0], q4[1], q4[2], q4[3], qa);

            const int bkb = kk * 32 + ((lane >> 3) & 1) * 16;
#pragma unroll
            for (int p = 0; p < 4; ++p) {
                uint32_t b4[2][2];
                const uint32_t ba = (p * 16 + brow_in) * FROWB + bkb;
                LDSM_X4(b4[0][0], b4[0][1], b4[1][0], b4[1][1], kP + ba);
#pragma unroll
                for (int u = 0; u < 2; ++u) {
                    float* cc = s[2 * p + u];
                    MMA_FP16(cc[0], cc[1], cc[2], cc[3],
                             q4[0], q4[1], q4[2], q4[3], b4[u][0], b4[u][1]);
                }
            }
        }

        // ---- mask add (prefetched) + online softmax ----
        {
            uint32_t mu[16];
            mu[0]  = mq0.x; mu[1]  = mq0.y; mu[2]  = mq0.z; mu[3]  = mq0.w;
            mu[4]  = mq1.x; mu[5]  = mq1.y; mu[6]  = mq1.z; mu[7]  = mq1.w;
            mu[8]  = mq2.x; mu[9]  = mq2.y; mu[10] = mq2.z; mu[11] = mq2.w;
            mu[12] = mq3.x; mu[13] = mq3.y; mu[14] = mq3.z; mu[15] = mq3.w;
#pragma unroll
            for (int t = 0; t < 8; ++t) {
                float2 lo2 = __bfloat1622float2(
                    *reinterpret_cast<__nv_bfloat162*>(&mu[2 * t]));
                float2 hi2 = __bfloat1622float2(
                    *reinterpret_cast<__nv_bfloat162*>(&mu[2 * t + 1]));
                s[t][0] += lo2.x; s[t][1] += lo2.y;
                s[t][2] += hi2.x; s[t][3] += hi2.y;
            }
        }

        float mx0 = -1e30f, mx1 = -1e30f;
#pragma unroll
        for (int t = 0; t < 8; ++t) {
            mx0 = fmaxf(mx0, fmaxf(s[t][0], s[t][1]));
            mx1 = fmaxf(mx1, fmaxf(s[t][2], s[t][3]));
        }
        mx0 = fmaxf(mx0, __shfl_xor_sync(0xffffffffu, mx0, 1));
        mx0 = fmaxf(mx0, __shfl_xor_sync(0xffffffffu, mx0, 2));
        mx1 = fmaxf(mx1, __shfl_xor_sync(0xffffffffu, mx1, 1));
        mx1 = fmaxf(mx1, __shfl_xor_sync(0xffffffffu, mx1, 2));

        const float mn0 = fmaxf(m0, mx0);
        const float mn1 = fmaxf(m1, mx1);
        const float a0 = __expf(m0 - mn0);
        const float a1 = __expf(m1 - mn1);
        m0 = mn0; m1 = mn1;

        float sum0 = 0.0f, sum1 = 0.0f;
#pragma unroll
        for (int t = 0; t < 8; ++t) {
            s[t][0] = __expf(s[t][0] - mn0);
            s[t][1] = __expf(s[t][1] - mn0);
            s[t][2] = __expf(s[t][2] - mn1);
            s[t][3] = __expf(s[t][3] - mn1);
            sum0 += s[t][0] + s[t][1];
            sum1 += s[t][2] + s[t][3];
        }
        sum0 += __shfl_xor_sync(0xffffffffu, sum0, 1);
        sum0 += __shfl_xor_sync(0xffffffffu, sum0, 2);
        sum1 += __shfl_xor_sync(0xffffffffu, sum1, 1);
        sum1 += __shfl_xor_sync(0xffffffffu, sum1, 2);
        l0 = l0 * a0 + sum0;
        l1 = l1 * a1 + sum1;

#pragma unroll
        for (int t = 0; t < 8; ++t) {
            o[t][0] *= a0; o[t][1] *= a0;
            o[t][2] *= a1; o[t][3] *= a1;
        }

        // ---- P fragments (fp16) ----
        uint32_t pH[4][4];
#pragma unroll
        for (int j = 0; j < 4; ++j) {
#pragma unroll
            for (int u = 0; u < 2; ++u) {
#pragma unroll
                for (int w = 0; w < 2; ++w) {
                    __half2 hh = __float22half2_rn(make_float2(
                        s[2 * j + w][2 * u + 0], s[2 * j + w][2 * u + 1]));
                    pH[j][2 * w + u] = *reinterpret_cast<uint32_t*>(&hh);
                }
            }
        }

        // ---- O += P @ V (fp16, 1 pass) ----
#pragma unroll
        for (int j = 0; j < 4; ++j) {
#pragma unroll
            for (int p = 0; p < 4; ++p) {
                uint32_t v4[2][2];
                const uint32_t va = (j * 16 + (lane & 15)) * FROWB
                                  + p * 32 + (lane >> 4) * 16;
                LDSM_X4_T(v4[0][0], v4[0][1], v4[1][0], v4[1][1], vP + va);
#pragma unroll
                for (int u = 0; u < 2; ++u) {
                    float* cc = o[2 * p + u];
                    MMA_FP16(cc[0], cc[1], cc[2], cc[3],
                             pH[j][0], pH[j][1], pH[j][2], pH[j][3],
                             v4[u][0], v4[u][1]);
                }
            }
        }
        // consumer release: last read of this KV stage was the V LDSM above
        if (lane == 0) MBAR_ARRIVE(mbE + 8 * (c & 3));
    }

    // ---- epilogue: normalize, write blocked single fp16 plane A ----
    const float inv0 = 1.0f / l0;
    const float inv1 = 1.0f / l1;
    const int grow = b * Tq + r0g;
#pragma unroll
    for (int t = 0; t < 8; ++t) {
        const int col = h * DHq + t * 8 + quadcol;
        {
            unsigned char* base = ap
                + ((size_t)((grow >> 7) * KCq + (col >> 5))) * XBLK
                + (grow & 127) * 80 + (col & 31) * 2;
            __half2 hh = __float22half2_rn(make_float2(o[t][0] * inv0, o[t][1] * inv0));
            *reinterpret_cast<uint32_t*>(base) = *reinterpret_cast<uint32_t*>(&hh);
        }
        {
            const int grow2 = grow + 8;
            unsigned char* base = ap
                + ((size_t)((grow2 >> 7) * KCq + (col >> 5))) * XBLK
                + (grow2 & 127) * 80 + (col & 31) * 2;
            __half2 hh = __float22half2_rn(make_float2(o[t][2] * inv1, o[t][3] * inv1));
            *reinterpret_cast<uint32_t*>(base) = *reinterpret_cast<uint32_t*>(&hh);
        }
    }
}

// ---------------------------------------------------------------------------
// kernel_launch
// Inputs: x, attention_mask, Wq, Wk, Wv, Wo, bo
// ---------------------------------------------------------------------------
extern "C" void kernel_launch(void* const* d_in, const int* in_sizes, int n_in,
                              void* d_out, int out_size)
{
    (void)in_sizes; (void)n_in; (void)out_size;
    const float* x    = (const float*)d_in[0];
    const float* mask = (const float*)d_in[1];
    const float* Wq   = (const float*)d_in[2];
    const float* Wk   = (const float*)d_in[3];
    const float* Wv   = (const float*)d_in[4];
    const float* Wo   = (const float*)d_in[5];
    const float* bo   = (const float*)d_in[6];
    float* out = (float*)d_out;

    unsigned char *xp, *ap, *w, *qb, *kpb, *vpb, *maskp;
    cudaGetSymbolAddress((void**)&xp, g_xp);
    cudaGetSymbolAddress((void**)&ap, g_ap);
    cudaGetSymbolAddress((void**)&w, g_w);
    cudaGetSymbolAddress((void**)&qb, g_qb);
    cudaGetSymbolAddress((void**)&kpb, g_kp);
    cudaGetSymbolAddress((void**)&vpb, g_vp);
    cudaGetSymbolAddress((void**)&maskp, g_maskp);

    const int M = Bq * Tq;     // 8192
    const int N = INNERq;      // 1024
    const int K = Dq;          // 1024
    const int nx = M * K;

    // Side stream: tsplit (weights) first, then mask permute.
    static cudaStream_t s2 = nullptr;
    static cudaEvent_t evFork = nullptr, evW = nullptr, evM = nullptr;
    if (s2 == nullptr) {
        cudaStreamCreateWithFlags(&s2, cudaStreamNonBlocking);
        cudaEventCreateWithFlags(&evFork, cudaEventDisableTiming);
        cudaEventCreateWithFlags(&evW, cudaEventDisableTiming);
        cudaEventCreateWithFlags(&evM, cudaEventDisableTiming);
    }

    cudaEventRecord(evFork, 0);
    cudaStreamWaitEvent(s2, evFork, 0);
    dim3 tGrid(N / 32, K / 32, 4), tBlk(32, 8);
    tsplit_kernel<<<tGrid, tBlk, 0, s2>>>(Wq, Wk, Wv, Wo, w, K, N);
    cudaEventRecord(evW, s2);
    dim3 mGrid(32, 16, Bq);
    mask_permute<<<mGrid, 256, 0, s2>>>(mask, maskp);
    cudaEventRecord(evM, s2);

    // main chain: x conversion (runs concurrently with tsplit/mask)
    split_kernel<<<nx / (256 * 4), 256>>>(x, xp);

    // join: QKV GEMM needs weights
    cudaStreamWaitEvent(0, evW, 0);

    // Q,K,V projections (one launch, 4-stage producer/consumer pipeline)
    cudaFuncSetAttribute(gemm_bulk_kernel,
                         cudaFuncAttributeMaxDynamicSharedMemorySize, GEMM_SMEM);
    dim3 qkvGrid(N / GBN, M / GBM, 3);
    gemm_bulk_kernel<<<qkvGrid, 256, GEMM_SMEM>>>(xp, w, qb, kpb, vpb,
                                                  nullptr, nullptr, M, N, K);

    // join: flash needs the permuted mask
    cudaStreamWaitEvent(0, evM, 0);

    // flash attention (pure fp16, 4-stage producer/consumer KV ring)
    cudaFuncSetAttribute(flash_mma_kernel,
                         cudaFuncAttributeMaxDynamicSharedMemorySize, FLASH_SMEM);
    dim3 fGrid(Tq / FBQ, Hq, Bq);
    flash_mma_kernel<<<fGrid, 256, FLASH_SMEM>>>(maskp, qb, kpb, vpb, ap);

    // output projection (fp32 + bias)
    dim3 oGrid(N / GBN, M / GBM, 1);
    gemm_bulk_kernel<<<oGrid, 256, GEMM_SMEM>>>(ap, w + 3 * WONE_BYTES,
                                                nullptr, nullptr, nullptr,
                                                out, bo, M, Dq, INNERq);
}